// round 16
// baseline (speedup 1.0000x reference)
#include <cuda_runtime.h>
#include <cuda_bf16.h>
#include <cstdint>

#define MAXN 100000
#define MAXE 1700000
#define DIN  128
#define HDIM 128
#define CDIM 47
#define CPAD 48
#define SCAN_B 256
#define NBLK_SCAN ((MAXN + SCAN_B - 1) / SCAN_B)

// ---------------- device scratch (allocation-free) ----------------
__device__ float g_h1[(size_t)MAXN * HDIM];
__device__ float g_h2[(size_t)MAXN * HDIM];
__device__ __nv_bfloat16 g_hn[(size_t)MAXN * HDIM];   // bf16 neighbor transform
__device__ float g_invdeg[MAXN];
__device__ int   g_deg[MAXN];
__device__ int   g_rowstart[MAXN + 1];
__device__ int   g_cursor[MAXN];
__device__ int   g_esrc[MAXE];
__device__ int   g_bsum[NBLK_SCAN];
__device__ int   g_boff[NBLK_SCAN];

// ---------------- degree / CSR build ----------------
__global__ void zero_deg_kernel(int n) {
    int i = blockIdx.x * blockDim.x + threadIdx.x;
    if (i < n) g_deg[i] = 0;
}

__global__ void count_deg_kernel(const int* __restrict__ dst, int e) {
    int i = blockIdx.x * blockDim.x + threadIdx.x;
    if (i < e) atomicAdd(&g_deg[dst[i]], 1);
}

__global__ void scan1_kernel(int n) {
    __shared__ int s[SCAN_B];
    int i = blockIdx.x * SCAN_B + threadIdx.x;
    int v = (i < n) ? g_deg[i] : 0;
    s[threadIdx.x] = v;
    __syncthreads();
    for (int off = 1; off < SCAN_B; off <<= 1) {
        int t = (threadIdx.x >= off) ? s[threadIdx.x - off] : 0;
        __syncthreads();
        s[threadIdx.x] += t;
        __syncthreads();
    }
    if (i < n) g_rowstart[i] = s[threadIdx.x] - v;
    if (threadIdx.x == SCAN_B - 1) g_bsum[blockIdx.x] = s[threadIdx.x];
}

__global__ void scan2_kernel(int nb) {
    __shared__ int s[512];
    int v = (threadIdx.x < nb) ? g_bsum[threadIdx.x] : 0;
    s[threadIdx.x] = v;
    __syncthreads();
    for (int off = 1; off < 512; off <<= 1) {
        int t = (threadIdx.x >= off) ? s[threadIdx.x - off] : 0;
        __syncthreads();
        s[threadIdx.x] += t;
        __syncthreads();
    }
    if (threadIdx.x < nb) g_boff[threadIdx.x] = s[threadIdx.x] - v;
}

// scan finalize + inverse degree (fused)
__global__ void scan3_kernel(int n, int e) {
    int i = blockIdx.x * blockDim.x + threadIdx.x;
    if (i < n) {
        int r = g_rowstart[i] + g_boff[i / SCAN_B];
        g_rowstart[i] = r;
        g_cursor[i] = r;
        g_invdeg[i] = 1.0f / fmaxf((float)g_deg[i], 1.0f);
    }
    if (i == 0) g_rowstart[n] = e;
}

__global__ void fill_kernel(const int* __restrict__ src, const int* __restrict__ dst, int e) {
    int i = blockIdx.x * blockDim.x + threadIdx.x;
    if (i < e) {
        int p = atomicAdd(&g_cursor[dst[i]], 1);
        g_esrc[p] = src[i];
    }
}

// ---------------- tf32 helpers ----------------
__device__ __forceinline__ uint32_t f2tf32(float x) {
    uint32_t r;
    asm("cvt.rna.tf32.f32 %0, %1;" : "=r"(r) : "f"(x));
    return r;
}

__device__ __forceinline__ void mma_tf32(float* c, const uint32_t* a, const uint32_t* b) {
    asm volatile(
        "mma.sync.aligned.m16n8k8.row.col.f32.tf32.tf32.f32 "
        "{%0,%1,%2,%3}, {%4,%5,%6,%7}, {%8,%9}, {%0,%1,%2,%3};"
        : "+f"(c[0]), "+f"(c[1]), "+f"(c[2]), "+f"(c[3])
        : "r"(a[0]), "r"(a[1]), "r"(a[2]), "r"(a[3]), "r"(b[0]), "r"(b[1]));
}

// ---------------- tf32 HMMA GEMM ----------------
// ysel: -1 -> blockIdx.y selects half; 0/1 -> fixed half.
// self half: out1 (float, stride DV) = A@W1 + bias
// neigh half: out2 (bf16, stride DVP) = A@W2
#define LDA 132
#define LDB 132

template<int BN, int DV, int DVP>
__global__ __launch_bounds__(256, 1)
void mma_gemm_kernel(const float* __restrict__ A,
                     const float* __restrict__ W1, const float* __restrict__ W2,
                     const float* __restrict__ bias,
                     float* __restrict__ out1, __nv_bfloat16* __restrict__ out2,
                     int nrows, int do_relu, int ysel) {
    extern __shared__ float smem[];
    float* As = smem;               // [128][LDA]
    float* Bs = smem + 128 * LDA;   // [BN][LDB]

    const int tid = threadIdx.x;
    const int row0 = blockIdx.x * 128;
    const bool selfhalf = (ysel >= 0) ? (ysel == 0) : (blockIdx.y == 0);
    const float* W = selfhalf ? W1 : W2;

    // ---- stage A: relu + tf32 round ----
    for (int f = tid; f < 128 * 32; f += 256) {
        int r = f >> 5;
        int c4 = (f & 31) * 4;
        int row = row0 + r;
        float4 v = make_float4(0.f, 0.f, 0.f, 0.f);
        if (row < nrows) {
            v = *(const float4*)&A[(size_t)row * DIN + c4];
            if (do_relu) {
                v.x = fmaxf(v.x, 0.f); v.y = fmaxf(v.y, 0.f);
                v.z = fmaxf(v.z, 0.f); v.w = fmaxf(v.w, 0.f);
            }
        }
        float* p = &As[r * LDA + c4];
        p[0] = __uint_as_float(f2tf32(v.x));
        p[1] = __uint_as_float(f2tf32(v.y));
        p[2] = __uint_as_float(f2tf32(v.z));
        p[3] = __uint_as_float(f2tf32(v.w));
    }

    // ---- stage B: Bs[n][k] = tf32(W[k][n]) ----
    for (int i = tid; i < 128 * BN; i += 256) {
        int n = i % BN;
        int k = i / BN;
        float v = (n < DV) ? W[(size_t)k * DV + n] : 0.f;
        Bs[n * LDB + k] = __uint_as_float(f2tf32(v));
    }
    __syncthreads();

    // ---- warp tiling ----
    constexpr int WN_CNT = BN / 64;
    constexpr int WM_CNT = 8 / WN_CNT;
    constexpr int TMR = 128 / WM_CNT;
    constexpr int MI = TMR / 16;

    const int wid = tid >> 5;
    const int lane = tid & 31;
    const int g = lane >> 2;
    const int tig = lane & 3;
    const int wm = wid % WM_CNT;
    const int wn = wid / WM_CNT;
    const int mbase = wm * TMR;
    const int nbase = wn * 64;

    float acc[MI][8][4];
#pragma unroll
    for (int mi = 0; mi < MI; mi++)
#pragma unroll
        for (int ni = 0; ni < 8; ni++)
#pragma unroll
            for (int q = 0; q < 4; q++) acc[mi][ni][q] = 0.f;

#pragma unroll
    for (int k0 = 0; k0 < 16; k0++) {
        const int kc = k0 * 8;
        uint32_t a[MI][4];
#pragma unroll
        for (int mi = 0; mi < MI; mi++) {
            int r = mbase + mi * 16 + g;
            a[mi][0] = __float_as_uint(As[r * LDA + kc + tig]);
            a[mi][1] = __float_as_uint(As[(r + 8) * LDA + kc + tig]);
            a[mi][2] = __float_as_uint(As[r * LDA + kc + tig + 4]);
            a[mi][3] = __float_as_uint(As[(r + 8) * LDA + kc + tig + 4]);
        }
        uint32_t b[8][2];
#pragma unroll
        for (int ni = 0; ni < 8; ni++) {
            int n = nbase + ni * 8 + g;
            b[ni][0] = __float_as_uint(Bs[n * LDB + kc + tig]);
            b[ni][1] = __float_as_uint(Bs[n * LDB + kc + tig + 4]);
        }
#pragma unroll
        for (int mi = 0; mi < MI; mi++)
#pragma unroll
            for (int ni = 0; ni < 8; ni++)
                mma_tf32(acc[mi][ni], a[mi], b[ni]);
    }

    // ---- epilogue ----
    constexpr bool VEC2 = (DV % 2 == 0);
#pragma unroll
    for (int mi = 0; mi < MI; mi++) {
#pragma unroll
        for (int ni = 0; ni < 8; ni++) {
            int col = nbase + ni * 8 + 2 * tig;   // even
            int r_lo = row0 + mbase + mi * 16 + g;
            int r_hi = r_lo + 8;
            if (selfhalf) {
                float badd0 = (col < DV) ? bias[col] : 0.f;
                float badd1 = (col + 1 < DV) ? bias[col + 1] : 0.f;
                if (r_lo < nrows) {
                    float v0 = acc[mi][ni][0] + badd0;
                    float v1 = acc[mi][ni][1] + badd1;
                    if (VEC2 && col + 1 < DV) {
                        *(float2*)&out1[(size_t)r_lo * DV + col] = make_float2(v0, v1);
                    } else {
                        if (col < DV)     out1[(size_t)r_lo * DV + col]     = v0;
                        if (col + 1 < DV) out1[(size_t)r_lo * DV + col + 1] = v1;
                    }
                }
                if (r_hi < nrows) {
                    float v0 = acc[mi][ni][2] + badd0;
                    float v1 = acc[mi][ni][3] + badd1;
                    if (VEC2 && col + 1 < DV) {
                        *(float2*)&out1[(size_t)r_hi * DV + col] = make_float2(v0, v1);
                    } else {
                        if (col < DV)     out1[(size_t)r_hi * DV + col]     = v0;
                        if (col + 1 < DV) out1[(size_t)r_hi * DV + col + 1] = v1;
                    }
                }
            } else {
                if (col < DVP) {
                    if (r_lo < nrows) {
                        __nv_bfloat162 v = __float22bfloat162_rn(
                            make_float2(acc[mi][ni][0], acc[mi][ni][1]));
                        *(__nv_bfloat162*)&out2[(size_t)r_lo * DVP + col] = v;
                    }
                    if (r_hi < nrows) {
                        __nv_bfloat162 v = __float22bfloat162_rn(
                            make_float2(acc[mi][ni][2], acc[mi][ni][3]));
                        *(__nv_bfloat162*)&out2[(size_t)r_hi * DVP + col] = v;
                    }
                }
            }
        }
    }
}

// ---------------- CSR gather aggregation (bf16 input, fp32 accum) ----------------
// 128-wide: 16 lanes per node, each lane owns 8 bf16 (16B uint4 loads).
__global__ void gather128_kernel(const __nv_bfloat16* __restrict__ hn,
                                 float* __restrict__ out, int n) {
    int gid = blockIdx.x * blockDim.x + threadIdx.x;
    int node = gid >> 4;
    if (node >= n) return;
    int l = gid & 15;
    int beg = g_rowstart[node];
    int end = g_rowstart[node + 1];
    const uint4* hrow = (const uint4*)hn;   // 16 uint4 per 128-col row
    float acc[8];
#pragma unroll
    for (int q = 0; q < 8; q++) acc[q] = 0.f;

    int j = beg;
    for (; j + 3 < end; j += 4) {
        int s0 = __ldg(&g_esrc[j]);
        int s1 = __ldg(&g_esrc[j + 1]);
        int s2 = __ldg(&g_esrc[j + 2]);
        int s3 = __ldg(&g_esrc[j + 3]);
        uint4 u0 = __ldg(&hrow[(size_t)s0 * 16 + l]);
        uint4 u1 = __ldg(&hrow[(size_t)s1 * 16 + l]);
        uint4 u2 = __ldg(&hrow[(size_t)s2 * 16 + l]);
        uint4 u3 = __ldg(&hrow[(size_t)s3 * 16 + l]);
#pragma unroll
        for (int h = 0; h < 4; h++) {
            uint4 u = (h == 0) ? u0 : (h == 1) ? u1 : (h == 2) ? u2 : u3;
            const uint32_t w[4] = {u.x, u.y, u.z, u.w};
#pragma unroll
            for (int q = 0; q < 4; q++) {
                float2 f = __bfloat1622float2(*(const __nv_bfloat162*)&w[q]);
                acc[q * 2 + 0] += f.x;
                acc[q * 2 + 1] += f.y;
            }
        }
    }
    for (; j < end; j++) {
        int s0 = __ldg(&g_esrc[j]);
        uint4 u = __ldg(&hrow[(size_t)s0 * 16 + l]);
        const uint32_t w[4] = {u.x, u.y, u.z, u.w};
#pragma unroll
        for (int q = 0; q < 4; q++) {
            float2 f = __bfloat1622float2(*(const __nv_bfloat162*)&w[q]);
            acc[q * 2 + 0] += f.x;
            acc[q * 2 + 1] += f.y;
        }
    }
    float inv = g_invdeg[node];
    float* orow = &out[(size_t)node * 128 + l * 8];
    float4 o0 = *(float4*)&orow[0];
    float4 o1 = *(float4*)&orow[4];
    o0.x += acc[0] * inv; o0.y += acc[1] * inv;
    o0.z += acc[2] * inv; o0.w += acc[3] * inv;
    o1.x += acc[4] * inv; o1.y += acc[5] * inv;
    o1.z += acc[6] * inv; o1.w += acc[7] * inv;
    *(float4*)&orow[0] = o0;
    *(float4*)&orow[4] = o1;
}

// 47-wide: hn rows padded to 48 bf16 (96B). Lanes 0..23 each own one bf16x2.
__global__ void gather47_kernel(const __nv_bfloat16* __restrict__ hn,
                                float* __restrict__ out, int n) {
    int gid = blockIdx.x * blockDim.x + threadIdx.x;
    int node = gid >> 5;
    if (node >= n) return;
    int lane = gid & 31;
    if (lane >= 24) return;
    int beg = g_rowstart[node];
    int end = g_rowstart[node + 1];
    float2 acc = make_float2(0.f, 0.f);
    int j = beg;
    for (; j + 3 < end; j += 4) {
        int s0 = __ldg(&g_esrc[j]);
        int s1 = __ldg(&g_esrc[j + 1]);
        int s2 = __ldg(&g_esrc[j + 2]);
        int s3 = __ldg(&g_esrc[j + 3]);
        uint32_t u0 = *(const uint32_t*)&hn[(size_t)s0 * CPAD + lane * 2];
        uint32_t u1 = *(const uint32_t*)&hn[(size_t)s1 * CPAD + lane * 2];
        uint32_t u2 = *(const uint32_t*)&hn[(size_t)s2 * CPAD + lane * 2];
        uint32_t u3 = *(const uint32_t*)&hn[(size_t)s3 * CPAD + lane * 2];
        float2 f0 = __bfloat1622float2(*(__nv_bfloat162*)&u0);
        float2 f1 = __bfloat1622float2(*(__nv_bfloat162*)&u1);
        float2 f2 = __bfloat1622float2(*(__nv_bfloat162*)&u2);
        float2 f3 = __bfloat1622float2(*(__nv_bfloat162*)&u3);
        acc.x += f0.x + f1.x + f2.x + f3.x;
        acc.y += f0.y + f1.y + f2.y + f3.y;
    }
    for (; j < end; j++) {
        int s0 = __ldg(&g_esrc[j]);
        uint32_t u0 = *(const uint32_t*)&hn[(size_t)s0 * CPAD + lane * 2];
        float2 f0 = __bfloat1622float2(*(__nv_bfloat162*)&u0);
        acc.x += f0.x; acc.y += f0.y;
    }
    float inv = g_invdeg[node];
    int c0 = lane * 2;
    float* orow = &out[(size_t)node * CDIM];
    orow[c0] += acc.x * inv;
    if (c0 + 1 < CDIM) orow[c0 + 1] += acc.y * inv;
}

// ---------------- launch ----------------
extern "C" void kernel_launch(void* const* d_in, const int* in_sizes, int n_in,
                              void* d_out, int out_size) {
    const float* x        = (const float*)d_in[0];
    const int*   src      = (const int*)d_in[1];
    const int*   dst      = (const int*)d_in[2];
    const float* w_self0  = (const float*)d_in[3];
    const float* w_neigh0 = (const float*)d_in[4];
    const float* b0       = (const float*)d_in[5];
    const float* w_self1  = (const float*)d_in[6];
    const float* w_neigh1 = (const float*)d_in[7];
    const float* b1       = (const float*)d_in[8];
    const float* w_self2  = (const float*)d_in[9];
    const float* w_neigh2 = (const float*)d_in[10];
    const float* b2       = (const float*)d_in[11];
    float* out = (float*)d_out;

    const int N = in_sizes[0] / DIN;
    const int E = in_sizes[1];

    void *p_h1, *p_h2, *p_hn;
    cudaGetSymbolAddress(&p_h1, g_h1);
    cudaGetSymbolAddress(&p_h2, g_h2);
    cudaGetSymbolAddress(&p_hn, g_hn);
    float* h1 = (float*)p_h1;
    float* h2 = (float*)p_h2;
    __nv_bfloat16* hn = (__nv_bfloat16*)p_hn;

    // one-time side stream + events (resource setup, identical work every call)
    static cudaStream_t s2 = [] {
        cudaStream_t s;
        cudaStreamCreateWithFlags(&s, cudaStreamNonBlocking);
        return s;
    }();
    static cudaEvent_t e1 = [] {
        cudaEvent_t e;
        cudaEventCreateWithFlags(&e, cudaEventDisableTiming);
        return e;
    }();
    static cudaEvent_t e2 = [] {
        cudaEvent_t e;
        cudaEventCreateWithFlags(&e, cudaEventDisableTiming);
        return e;
    }();

    const int SMEM128 = (128 * LDA + 128 * LDB) * sizeof(float);  // 135168
    const int SMEM64  = (128 * LDA + 64 * LDB)  * sizeof(float);  // 101376
    cudaFuncSetAttribute(mma_gemm_kernel<128, 128, 128>,
                         cudaFuncAttributeMaxDynamicSharedMemorySize, SMEM128);
    cudaFuncSetAttribute(mma_gemm_kernel<64, 47, 48>,
                         cudaFuncAttributeMaxDynamicSharedMemorySize, SMEM64);

    dim3 blk(256);
    int nblk = (N + 255) / 256;
    int eblk = (E + 255) / 256;
    int nb_scan = (N + SCAN_B - 1) / SCAN_B;
    int g128blk = (int)(((long long)N * 16 + 255) / 256);
    int g47blk  = (int)(((long long)N * 32 + 255) / 256);
    int mblk = (N + 127) / 128;
    dim3 gg(mblk, 2);
    dim3 g1(mblk, 1);

    // fork: layer-0 GEMMs (independent of CSR) run on s2, CSR chain on default.
    cudaEventRecord(e1, 0);
    cudaStreamWaitEvent(s2, e1, 0);

    zero_deg_kernel<<<nblk, blk>>>(N);                                     // (1)
    mma_gemm_kernel<128, 128, 128><<<g1, blk, SMEM128, s2>>>(
        x, w_self0, w_neigh0, b0, h1, hn, N, 0, 0);                        // (2) self
    count_deg_kernel<<<eblk, blk>>>(dst, E);                               // (3)
    mma_gemm_kernel<128, 128, 128><<<g1, blk, SMEM128, s2>>>(
        x, w_self0, w_neigh0, b0, h1, hn, N, 0, 1);                        // (4) neigh (profiled)
    scan1_kernel<<<nb_scan, SCAN_B>>>(N);                                  // (5)
    scan2_kernel<<<1, 512>>>(nb_scan);                                     // (6)
    scan3_kernel<<<nblk, blk>>>(N, E);                                     // (7)
    fill_kernel<<<eblk, blk>>>(src, dst, E);                               // (8)

    // join: gather needs CSR (default) + gemm0 (s2)
    cudaEventRecord(e2, s2);
    cudaStreamWaitEvent(0, e2, 0);

    gather128_kernel<<<g128blk, blk>>>(hn, h1, N);

    // layer 1: relu(h1) -> h2, hn
    mma_gemm_kernel<128, 128, 128><<<gg, blk, SMEM128>>>(h1, w_self1, w_neigh1, b1,
                                                         h2, hn, N, 1, -1);
    gather128_kernel<<<g128blk, blk>>>(hn, h2, N);

    // layer 2: relu(h2) -> out (N x 47 fp32), hn (N x 48 bf16)
    mma_gemm_kernel<64, 47, 48><<<gg, blk, SMEM64>>>(h2, w_self2, w_neigh2, b2,
                                                     out, hn, N, 1, -1);
    gather47_kernel<<<g47blk, blk>>>(hn, out, N);
}